// round 13
// baseline (speedup 1.0000x reference)
#include <cuda_runtime.h>
#include <cuda_bf16.h>
#include <cuda_fp16.h>
#include <cstdint>

// Problem constants (shapes fixed by the reference generator)
#define NNODES 100000
#define NEDGES 1600000
#define FDIM   128

// ---------------- scratch (static device allocations; no cudaMalloc) --------
__device__ __half d_h16[NNODES * FDIM];  // GEMM output, fp16 (gather source)
__device__ float  d_g[NNODES * FDIM];    // layer-1 aggregated+relu output (fp32)
__device__ float  d_dinv[NNODES];
__device__ int    d_cnt[NNODES];
__device__ int    d_rowptr[NNODES + 1];
__device__ int    d_cursor[NNODES];
__device__ int    d_bsum[1024];
__device__ int    d_csrc[NEDGES];
__device__ float  d_cnorm[NEDGES];
// W pre-converted to bf16 hi/lo, stored as B[j][k] = W[k][j] (row-major, K contiguous)
__device__ __align__(16) __nv_bfloat16 d_w1hi[16384];
__device__ __align__(16) __nv_bfloat16 d_w1lo[16384];
__device__ __align__(16) __nv_bfloat16 d_w2hi[16384];
__device__ __align__(16) __nv_bfloat16 d_w2lo[16384];

// ---------------- degree / count ---------------------------------------------
__global__ void count_kernel(const int* __restrict__ dst, int E) {
    int e = blockIdx.x * blockDim.x + threadIdx.x;
    if (e < E) atomicAdd(&d_cnt[dst[e]], 1);
}

// ---------------- CSR build: 3-kernel exclusive scan + scatter --------------
__global__ void scan1_kernel(int n) {
    __shared__ int sh[1024];
    int t = threadIdx.x;
    int i = blockIdx.x * 1024 + t;
    int v = (i < n) ? d_cnt[i] : 0;
    sh[t] = v;
    __syncthreads();
    #pragma unroll
    for (int off = 1; off < 1024; off <<= 1) {
        int x = (t >= off) ? sh[t - off] : 0;
        __syncthreads();
        sh[t] += x;
        __syncthreads();
    }
    if (i < n) d_rowptr[i] = sh[t] - v;
    if (t == 1023) d_bsum[blockIdx.x] = sh[t];
}
__global__ void scan2_kernel(int nb) {
    __shared__ int sh[1024];
    int t = threadIdx.x;
    int v = (t < nb) ? d_bsum[t] : 0;
    sh[t] = v;
    __syncthreads();
    #pragma unroll
    for (int off = 1; off < 1024; off <<= 1) {
        int x = (t >= off) ? sh[t - off] : 0;
        __syncthreads();
        sh[t] += x;
        __syncthreads();
    }
    if (t < nb) d_bsum[t] = sh[t] - v;
}
// scan3 + dinv fused
__global__ void scan3_kernel(int n, int E) {
    int i = blockIdx.x * blockDim.x + threadIdx.x;
    if (i < n) {
        int r = d_rowptr[i] + d_bsum[i >> 10];
        d_rowptr[i] = r;
        d_cursor[i] = r;
        d_dinv[i] = rsqrtf((float)d_cnt[i] + 1.0f);
    }
    if (i == 0) d_rowptr[n] = E;
}
__global__ void scatter_kernel(const int* __restrict__ src,
                               const int* __restrict__ dst, int E) {
    int e = blockIdx.x * blockDim.x + threadIdx.x;
    if (e < E) {
        int s = src[e], d = dst[e];
        int p = atomicAdd(&d_cursor[d], 1);
        d_csrc[p]  = s;
        d_cnorm[p] = d_dinv[s] * d_dinv[d];
    }
}

// ---------------- W pre-convert: fp32 [K,N] -> bf16 hi/lo B[j][k] -----------
__global__ void prep_w_kernel(const float* __restrict__ W1,
                              const float* __restrict__ W2) {
    int idx = blockIdx.x * blockDim.x + threadIdx.x;   // 0..32767
    if (idx >= 2 * 16384) return;
    int which = idx >> 14;
    int e = idx & 16383;
    int j = e >> 7;      // output feature (B row)
    int k = e & 127;     // input dim (B col, contiguous)
    const float* W = which ? W2 : W1;
    float w = W[k * 128 + j];
    __nv_bfloat16 hi = __float2bfloat16(w);
    __nv_bfloat16 lo = __float2bfloat16(w - __bfloat162float(hi));
    if (which) { d_w2hi[e] = hi; d_w2lo[e] = lo; }
    else       { d_w1hi[e] = hi; d_w1lo[e] = lo; }
}

// ---------------- tensor-core GEMM via mma.sync (HMMA bf16) ------------------
// Out16[n,128] = fp16( X[n,128] @ W ), fp32 accuracy via bf16 3-term split.
// CTA tile 128x128, 512 threads = 16 warps, warp tile 32x32 (2 m-tiles x 4 n-tiles).
#define APADW 68           // padded row stride in 32-bit words (136 bf16)
#define TILE_WORDS (128 * APADW)

__device__ __forceinline__ void mma16816(float* c, const uint32_t* a, const uint32_t* b) {
    asm volatile(
        "mma.sync.aligned.m16n8k16.row.col.f32.bf16.bf16.f32 "
        "{%0,%1,%2,%3}, {%4,%5,%6,%7}, {%8,%9}, {%0,%1,%2,%3};"
        : "+f"(c[0]), "+f"(c[1]), "+f"(c[2]), "+f"(c[3])
        : "r"(a[0]), "r"(a[1]), "r"(a[2]), "r"(a[3]), "r"(b[0]), "r"(b[1]));
}

__global__ void __launch_bounds__(512, 1)
gemm_mma_kernel(const float* __restrict__ X,
                const __nv_bfloat16* __restrict__ Bhi_g,
                const __nv_bfloat16* __restrict__ Blo_g,
                __half* __restrict__ Out16, int n) {
    extern __shared__ uint32_t sm[];
    uint32_t* Ahi = sm;
    uint32_t* Alo = sm + TILE_WORDS;
    uint32_t* Bh  = sm + 2 * TILE_WORDS;
    uint32_t* Bl  = sm + 3 * TILE_WORDS;

    int tid  = threadIdx.x;
    int row0 = blockIdx.x * 128;

    // Copy W hi/lo tiles (128x128 bf16 = 8192 words) into padded SMEM
    {
        const uint32_t* gh = reinterpret_cast<const uint32_t*>(Bhi_g);
        const uint32_t* gl = reinterpret_cast<const uint32_t*>(Blo_g);
        #pragma unroll
        for (int i = tid; i < 8192; i += 512) {
            int r = i >> 6, c = i & 63;
            Bh[r * APADW + c] = gh[i];
            Bl[r * APADW + c] = gl[i];
        }
    }
    // Convert this tile's X rows to bf16 hi/lo into padded SMEM
    {
        int r = tid >> 2;            // 0..127
        int q = tid & 3;             // 32-col quarter
        int gr = row0 + r;
        #pragma unroll
        for (int c = q * 32; c < q * 32 + 32; c += 4) {
            float4 x4 = make_float4(0.f, 0.f, 0.f, 0.f);
            if (gr < n)
                x4 = *reinterpret_cast<const float4*>(X + (size_t)gr * 128 + c);
            __nv_bfloat16 h0 = __float2bfloat16(x4.x);
            __nv_bfloat16 h1 = __float2bfloat16(x4.y);
            __nv_bfloat16 h2 = __float2bfloat16(x4.z);
            __nv_bfloat16 h3 = __float2bfloat16(x4.w);
            __nv_bfloat16 l0 = __float2bfloat16(x4.x - __bfloat162float(h0));
            __nv_bfloat16 l1 = __float2bfloat16(x4.y - __bfloat162float(h1));
            __nv_bfloat16 l2 = __float2bfloat16(x4.z - __bfloat162float(h2));
            __nv_bfloat16 l3 = __float2bfloat16(x4.w - __bfloat162float(h3));
            uint32_t ph0 = (uint32_t)__bfloat16_as_ushort(h0) | ((uint32_t)__bfloat16_as_ushort(h1) << 16);
            uint32_t ph1 = (uint32_t)__bfloat16_as_ushort(h2) | ((uint32_t)__bfloat16_as_ushort(h3) << 16);
            uint32_t pl0 = (uint32_t)__bfloat16_as_ushort(l0) | ((uint32_t)__bfloat16_as_ushort(l1) << 16);
            uint32_t pl1 = (uint32_t)__bfloat16_as_ushort(l2) | ((uint32_t)__bfloat16_as_ushort(l3) << 16);
            int wo = r * APADW + (c >> 1);
            Ahi[wo]     = ph0;  Ahi[wo + 1] = ph1;
            Alo[wo]     = pl0;  Alo[wo + 1] = pl1;
        }
    }
    __syncthreads();

    // Warp tiling: 16 warps, warp w covers rows (w&3)*32, cols (w>>2)*32
    int w    = tid >> 5;
    int lane = tid & 31;
    int gid  = lane >> 2;    // 0..7
    int tig  = lane & 3;     // 0..3
    int m0 = (w & 3) * 32;
    int n0 = (w >> 2) * 32;

    float acc[2][4][4];
    #pragma unroll
    for (int mt = 0; mt < 2; mt++)
        #pragma unroll
        for (int nt = 0; nt < 4; nt++)
            #pragma unroll
            for (int q = 0; q < 4; q++) acc[mt][nt][q] = 0.f;

    #pragma unroll
    for (int kc = 0; kc < 128; kc += 16) {
        int kw = kc >> 1;                    // word offset of k-chunk base
        uint32_t a_hi[2][4], a_lo[2][4], bfr[4][2];
        #pragma unroll
        for (int mt = 0; mt < 2; mt++) {
            int base = (m0 + mt * 16 + gid) * APADW + kw + tig;
            a_hi[mt][0] = Ahi[base];
            a_hi[mt][1] = Ahi[base + 8 * APADW];
            a_hi[mt][2] = Ahi[base + 4];
            a_hi[mt][3] = Ahi[base + 8 * APADW + 4];
            a_lo[mt][0] = Alo[base];
            a_lo[mt][1] = Alo[base + 8 * APADW];
            a_lo[mt][2] = Alo[base + 4];
            a_lo[mt][3] = Alo[base + 8 * APADW + 4];
        }
        // B hi: terms hi*hi and lo*hi
        #pragma unroll
        for (int nt = 0; nt < 4; nt++) {
            int base = (n0 + nt * 8 + gid) * APADW + kw + tig;
            bfr[nt][0] = Bh[base];
            bfr[nt][1] = Bh[base + 4];
        }
        #pragma unroll
        for (int mt = 0; mt < 2; mt++)
            #pragma unroll
            for (int nt = 0; nt < 4; nt++) {
                mma16816(acc[mt][nt], a_hi[mt], bfr[nt]);
                mma16816(acc[mt][nt], a_lo[mt], bfr[nt]);
            }
        // B lo: term hi*lo
        #pragma unroll
        for (int nt = 0; nt < 4; nt++) {
            int base = (n0 + nt * 8 + gid) * APADW + kw + tig;
            bfr[nt][0] = Bl[base];
            bfr[nt][1] = Bl[base + 4];
        }
        #pragma unroll
        for (int mt = 0; mt < 2; mt++)
            #pragma unroll
            for (int nt = 0; nt < 4; nt++)
                mma16816(acc[mt][nt], a_hi[mt], bfr[nt]);
    }

    // Epilogue: write fp16. c0,c1 -> (row=gid, cols tig*2+{0,1}); c2,c3 -> row=gid+8
    #pragma unroll
    for (int mt = 0; mt < 2; mt++) {
        int gr0 = row0 + m0 + mt * 16 + gid;
        #pragma unroll
        for (int nt = 0; nt < 4; nt++) {
            int col = n0 + nt * 8 + tig * 2;
            if (gr0 < n)
                *reinterpret_cast<__half2*>(Out16 + (size_t)gr0 * 128 + col) =
                    __floats2half2_rn(acc[mt][nt][0], acc[mt][nt][1]);
            if (gr0 + 8 < n)
                *reinterpret_cast<__half2*>(Out16 + (size_t)(gr0 + 8) * 128 + col) =
                    __floats2half2_rn(acc[mt][nt][2], acc[mt][nt][3]);
        }
    }
}

// ---------------- CSR aggregation (fp16 gather, unroll-4 for MLP) -----------
__device__ __forceinline__ void acc_edge(float4& acc, uint2 v, float wv) {
    float2 fa = __half22float2(*reinterpret_cast<__half2*>(&v.x));
    float2 fb = __half22float2(*reinterpret_cast<__half2*>(&v.y));
    acc.x += fa.x * wv;
    acc.y += fa.y * wv;
    acc.z += fb.x * wv;
    acc.w += fb.y * wv;
}

__device__ __forceinline__ float4 agg_row(const __half* __restrict__ h16,
                                          const float* __restrict__ bias,
                                          int i, int lane) {
    const uint2* h2 = reinterpret_cast<const uint2*>(h16);   // 32 uint2 per row
    int start = d_rowptr[i];
    int end   = d_rowptr[i + 1];
    float4 acc = make_float4(0.f, 0.f, 0.f, 0.f);

    for (int base = start; base < end; base += 32) {
        int cnt = min(32, end - base);
        int idx = 0; float nm = 0.f;
        if (lane < cnt) {
            idx = d_csrc[base + lane];
            nm  = d_cnorm[base + lane];
        }
        int j = 0;
        // Unroll by 4: issue 4 independent gathers before consuming (MLP=4)
        for (; j + 4 <= cnt; j += 4) {
            int   s0 = __shfl_sync(0xffffffffu, idx, j);
            int   s1 = __shfl_sync(0xffffffffu, idx, j + 1);
            int   s2 = __shfl_sync(0xffffffffu, idx, j + 2);
            int   s3 = __shfl_sync(0xffffffffu, idx, j + 3);
            float w0 = __shfl_sync(0xffffffffu, nm, j);
            float w1 = __shfl_sync(0xffffffffu, nm, j + 1);
            float w2 = __shfl_sync(0xffffffffu, nm, j + 2);
            float w3 = __shfl_sync(0xffffffffu, nm, j + 3);
            uint2 v0 = h2[(size_t)s0 * 32 + lane];
            uint2 v1 = h2[(size_t)s1 * 32 + lane];
            uint2 v2 = h2[(size_t)s2 * 32 + lane];
            uint2 v3 = h2[(size_t)s3 * 32 + lane];
            acc_edge(acc, v0, w0);
            acc_edge(acc, v1, w1);
            acc_edge(acc, v2, w2);
            acc_edge(acc, v3, w3);
        }
        for (; j < cnt; j++) {
            int   s = __shfl_sync(0xffffffffu, idx, j);
            float wv = __shfl_sync(0xffffffffu, nm, j);
            uint2 v = h2[(size_t)s * 32 + lane];
            acc_edge(acc, v, wv);
        }
    }
    float di = d_dinv[i];
    float d2 = di * di;
    uint2 sv = h2[(size_t)i * 32 + lane];
    float2 sa = __half22float2(*reinterpret_cast<__half2*>(&sv.x));
    float2 sb = __half22float2(*reinterpret_cast<__half2*>(&sv.y));
    const float4 bv = reinterpret_cast<const float4*>(bias)[lane];
    acc.x = fmaxf(acc.x + sa.x * d2 + bv.x, 0.f);
    acc.y = fmaxf(acc.y + sa.y * d2 + bv.y, 0.f);
    acc.z = fmaxf(acc.z + sb.x * d2 + bv.z, 0.f);
    acc.w = fmaxf(acc.w + sb.y * d2 + bv.w, 0.f);
    return acc;
}

__global__ __launch_bounds__(256)
void agg_kernel(const __half* __restrict__ h16, const float* __restrict__ bias,
                float* __restrict__ out, int n) {
    int lane   = threadIdx.x & 31;
    int warp   = (blockIdx.x * blockDim.x + threadIdx.x) >> 5;
    int nwarps = (gridDim.x * blockDim.x) >> 5;
    for (int i = warp; i < n; i += nwarps) {
        float4 acc = agg_row(h16, bias, i, lane);
        reinterpret_cast<float4*>(out)[(size_t)i * 32 + lane] = acc;
    }
}

// Layer-2 agg with fused readout: out[i] = relu(agg_row) . Wlin + blin
__global__ __launch_bounds__(256)
void agg_final_kernel(const __half* __restrict__ h16, const float* __restrict__ bias,
                      const float* __restrict__ wlin, const float* __restrict__ blin,
                      float* __restrict__ out, int n) {
    int lane   = threadIdx.x & 31;
    int warp   = (blockIdx.x * blockDim.x + threadIdx.x) >> 5;
    int nwarps = (gridDim.x * blockDim.x) >> 5;
    for (int i = warp; i < n; i += nwarps) {
        float4 acc = agg_row(h16, bias, i, lane);
        float4 wv = reinterpret_cast<const float4*>(wlin)[lane];
        float s = acc.x * wv.x + acc.y * wv.y + acc.z * wv.z + acc.w * wv.w;
        #pragma unroll
        for (int off = 16; off > 0; off >>= 1)
            s += __shfl_xor_sync(0xffffffffu, s, off);
        if (lane == 0) out[i] = s + blin[0];
    }
}

// ---------------- launch ----------------------------------------------------
extern "C" void kernel_launch(void* const* d_in, const int* in_sizes, int n_in,
                              void* d_out, int out_size) {
    const float* x    = (const float*)d_in[0];
    const int*   ei   = (const int*)d_in[1];
    const float* W1   = (const float*)d_in[2];
    const float* b1   = (const float*)d_in[3];
    const float* W2   = (const float*)d_in[4];
    const float* b2   = (const float*)d_in[5];
    const float* Wlin = (const float*)d_in[6];
    const float* blin = (const float*)d_in[7];
    float* out = (float*)d_out;

    int E = in_sizes[1] / 2;
    int n = in_sizes[0] / FDIM;
    const int* src = ei;
    const int* dst = ei + E;

    int nB = (n + 255) / 256;
    int eB = (E + 255) / 256;
    int nb = (n + 1023) / 1024;
    int gB = (n + 127) / 128;

    __half* h16;  cudaGetSymbolAddress((void**)&h16, d_h16);
    float*  gbuf; cudaGetSymbolAddress((void**)&gbuf, d_g);
    int*    cntp; cudaGetSymbolAddress((void**)&cntp, d_cnt);
    __nv_bfloat16 *w1hi, *w1lo, *w2hi, *w2lo;
    cudaGetSymbolAddress((void**)&w1hi, d_w1hi);
    cudaGetSymbolAddress((void**)&w1lo, d_w1lo);
    cudaGetSymbolAddress((void**)&w2hi, d_w2hi);
    cudaGetSymbolAddress((void**)&w2lo, d_w2lo);

    const int GEMM_SMEM = 4 * TILE_WORDS * 4;   // 139264 bytes
    cudaFuncSetAttribute(gemm_mma_kernel,
                         cudaFuncAttributeMaxDynamicSharedMemorySize, GEMM_SMEM);

    // One-time side-stream + events for CSR/GEMM overlap (handles only; no
    // device-memory APIs). Work launched per call is identical every call.
    static cudaStream_t s2 = nullptr;
    static cudaEvent_t ev_fork = nullptr, ev_join = nullptr;
    static int sinit = 0;
    if (!sinit) {
        if (cudaStreamCreateWithFlags(&s2, cudaStreamNonBlocking) != cudaSuccess)
            s2 = nullptr;
        if (s2) {
            cudaEventCreateWithFlags(&ev_fork, cudaEventDisableTiming);
            cudaEventCreateWithFlags(&ev_join, cudaEventDisableTiming);
        }
        sinit = 1;
    }

    if (s2) {
        // Fork: CSR build on s2, W-prep + GEMM-1 on the main stream.
        cudaEventRecord(ev_fork, 0);
        cudaStreamWaitEvent(s2, ev_fork, 0);

        cudaMemsetAsync(cntp, 0, (size_t)n * sizeof(int), s2);
        count_kernel<<<eB, 256, 0, s2>>>(dst, E);
        scan1_kernel<<<nb, 1024, 0, s2>>>(n);
        scan2_kernel<<<1, 1024, 0, s2>>>(nb);
        scan3_kernel<<<nB, 256, 0, s2>>>(n, E);
        scatter_kernel<<<eB, 256, 0, s2>>>(src, dst, E);
        cudaEventRecord(ev_join, s2);

        prep_w_kernel<<<128, 256>>>(W1, W2);
        gemm_mma_kernel<<<gB, 512, GEMM_SMEM>>>(x, w1hi, w1lo, h16, n);

        // Join: agg needs both GEMM-1 output and the CSR structure.
        cudaStreamWaitEvent(0, ev_join, 0);
    } else {
        // Fallback: sequential single-stream
        cudaMemsetAsync(cntp, 0, (size_t)n * sizeof(int));
        count_kernel<<<eB, 256>>>(dst, E);
        scan1_kernel<<<nb, 1024>>>(n);
        scan2_kernel<<<1, 1024>>>(nb);
        scan3_kernel<<<nB, 256>>>(n, E);
        scatter_kernel<<<eB, 256>>>(src, dst, E);
        prep_w_kernel<<<128, 256>>>(W1, W2);
        gemm_mma_kernel<<<gB, 512, GEMM_SMEM>>>(x, w1hi, w1lo, h16, n);
    }

    agg_kernel<<<2048, 256>>>(h16, b1, gbuf, n);
    // layer 2
    gemm_mma_kernel<<<gB, 512, GEMM_SMEM>>>(gbuf, w2hi, w2lo, h16, n);
    agg_final_kernel<<<2048, 256>>>(h16, b2, Wlin, blin, out, n);
    (void)n_in; (void)out_size;
}

// round 14
// speedup vs baseline: 1.5095x; 1.5095x over previous
#include <cuda_runtime.h>
#include <cuda_bf16.h>
#include <cuda_fp16.h>
#include <cstdint>

// Problem constants (shapes fixed by the reference generator)
#define NNODES 100000
#define NEDGES 1600000
#define FDIM   128

// ---------------- scratch (static device allocations; no cudaMalloc) --------
__device__ __half d_h16[NNODES * FDIM];  // GEMM output, fp16 (gather source)
__device__ float  d_g[NNODES * FDIM];    // layer-1 aggregated+relu output (fp32)
__device__ float  d_dinv[NNODES];
__device__ int    d_cnt[NNODES];
__device__ int    d_rowptr[NNODES + 1];
__device__ int    d_cursor[NNODES];
__device__ int    d_bsum[1024];
__device__ int2   d_edge[NEDGES];        // packed {src, norm-as-int} per CSR slot
// W pre-converted to bf16 hi/lo, stored as B[j][k] = W[k][j] (row-major, K contiguous)
__device__ __align__(16) __nv_bfloat16 d_w1hi[16384];
__device__ __align__(16) __nv_bfloat16 d_w1lo[16384];
__device__ __align__(16) __nv_bfloat16 d_w2hi[16384];
__device__ __align__(16) __nv_bfloat16 d_w2lo[16384];

// ---------------- degree / count ---------------------------------------------
__global__ void count_kernel(const int* __restrict__ dst, int E) {
    int e = blockIdx.x * blockDim.x + threadIdx.x;
    if (e < E) atomicAdd(&d_cnt[dst[e]], 1);
}

// ---------------- CSR build: 3-kernel exclusive scan + scatter --------------
__global__ void scan1_kernel(int n) {
    __shared__ int sh[1024];
    int t = threadIdx.x;
    int i = blockIdx.x * 1024 + t;
    int v = (i < n) ? d_cnt[i] : 0;
    sh[t] = v;
    __syncthreads();
    #pragma unroll
    for (int off = 1; off < 1024; off <<= 1) {
        int x = (t >= off) ? sh[t - off] : 0;
        __syncthreads();
        sh[t] += x;
        __syncthreads();
    }
    if (i < n) d_rowptr[i] = sh[t] - v;
    if (t == 1023) d_bsum[blockIdx.x] = sh[t];
}
__global__ void scan2_kernel(int nb) {
    __shared__ int sh[1024];
    int t = threadIdx.x;
    int v = (t < nb) ? d_bsum[t] : 0;
    sh[t] = v;
    __syncthreads();
    #pragma unroll
    for (int off = 1; off < 1024; off <<= 1) {
        int x = (t >= off) ? sh[t - off] : 0;
        __syncthreads();
        sh[t] += x;
        __syncthreads();
    }
    if (t < nb) d_bsum[t] = sh[t] - v;
}
// scan3 + dinv fused
__global__ void scan3_kernel(int n, int E) {
    int i = blockIdx.x * blockDim.x + threadIdx.x;
    if (i < n) {
        int r = d_rowptr[i] + d_bsum[i >> 10];
        d_rowptr[i] = r;
        d_cursor[i] = r;
        d_dinv[i] = rsqrtf((float)d_cnt[i] + 1.0f);
    }
    if (i == 0) d_rowptr[n] = E;
}
__global__ void scatter_kernel(const int* __restrict__ src,
                               const int* __restrict__ dst, int E) {
    int e = blockIdx.x * blockDim.x + threadIdx.x;
    if (e < E) {
        int s = src[e], d = dst[e];
        int p = atomicAdd(&d_cursor[d], 1);
        float nm = d_dinv[s] * d_dinv[d];
        d_edge[p] = make_int2(s, __float_as_int(nm));
    }
}

// ---------------- W pre-convert: fp32 [K,N] -> bf16 hi/lo B[j][k] -----------
__global__ void prep_w_kernel(const float* __restrict__ W1,
                              const float* __restrict__ W2) {
    int idx = blockIdx.x * blockDim.x + threadIdx.x;   // 0..32767
    if (idx >= 2 * 16384) return;
    int which = idx >> 14;
    int e = idx & 16383;
    int j = e >> 7;      // output feature (B row)
    int k = e & 127;     // input dim (B col, contiguous)
    const float* W = which ? W2 : W1;
    float w = W[k * 128 + j];
    __nv_bfloat16 hi = __float2bfloat16(w);
    __nv_bfloat16 lo = __float2bfloat16(w - __bfloat162float(hi));
    if (which) { d_w2hi[e] = hi; d_w2lo[e] = lo; }
    else       { d_w1hi[e] = hi; d_w1lo[e] = lo; }
}

// ---------------- tensor-core GEMM via mma.sync (HMMA bf16) ------------------
// Out16[n,128] = fp16( X[n,128] @ W ), fp32 accuracy via bf16 3-term split.
// CTA tile 128x128, 512 threads = 16 warps, warp tile 32x32 (2 m-tiles x 4 n-tiles).
#define APADW 68           // padded row stride in 32-bit words (136 bf16)
#define TILE_WORDS (128 * APADW)

__device__ __forceinline__ void mma16816(float* c, const uint32_t* a, const uint32_t* b) {
    asm volatile(
        "mma.sync.aligned.m16n8k16.row.col.f32.bf16.bf16.f32 "
        "{%0,%1,%2,%3}, {%4,%5,%6,%7}, {%8,%9}, {%0,%1,%2,%3};"
        : "+f"(c[0]), "+f"(c[1]), "+f"(c[2]), "+f"(c[3])
        : "r"(a[0]), "r"(a[1]), "r"(a[2]), "r"(a[3]), "r"(b[0]), "r"(b[1]));
}

__global__ void __launch_bounds__(512, 1)
gemm_mma_kernel(const float* __restrict__ X,
                const __nv_bfloat16* __restrict__ Bhi_g,
                const __nv_bfloat16* __restrict__ Blo_g,
                __half* __restrict__ Out16, int n) {
    extern __shared__ uint32_t sm[];
    uint32_t* Ahi = sm;
    uint32_t* Alo = sm + TILE_WORDS;
    uint32_t* Bh  = sm + 2 * TILE_WORDS;
    uint32_t* Bl  = sm + 3 * TILE_WORDS;

    int tid  = threadIdx.x;
    int row0 = blockIdx.x * 128;

    // Copy W hi/lo tiles (128x128 bf16 = 8192 words) into padded SMEM
    {
        const uint32_t* gh = reinterpret_cast<const uint32_t*>(Bhi_g);
        const uint32_t* gl = reinterpret_cast<const uint32_t*>(Blo_g);
        #pragma unroll
        for (int i = tid; i < 8192; i += 512) {
            int r = i >> 6, c = i & 63;
            Bh[r * APADW + c] = gh[i];
            Bl[r * APADW + c] = gl[i];
        }
    }
    // Convert this tile's X rows to bf16 hi/lo into padded SMEM
    {
        int r = tid >> 2;            // 0..127
        int q = tid & 3;             // 32-col quarter
        int gr = row0 + r;
        #pragma unroll
        for (int c = q * 32; c < q * 32 + 32; c += 4) {
            float4 x4 = make_float4(0.f, 0.f, 0.f, 0.f);
            if (gr < n)
                x4 = *reinterpret_cast<const float4*>(X + (size_t)gr * 128 + c);
            __nv_bfloat16 h0 = __float2bfloat16(x4.x);
            __nv_bfloat16 h1 = __float2bfloat16(x4.y);
            __nv_bfloat16 h2 = __float2bfloat16(x4.z);
            __nv_bfloat16 h3 = __float2bfloat16(x4.w);
            __nv_bfloat16 l0 = __float2bfloat16(x4.x - __bfloat162float(h0));
            __nv_bfloat16 l1 = __float2bfloat16(x4.y - __bfloat162float(h1));
            __nv_bfloat16 l2 = __float2bfloat16(x4.z - __bfloat162float(h2));
            __nv_bfloat16 l3 = __float2bfloat16(x4.w - __bfloat162float(h3));
            uint32_t ph0 = (uint32_t)__bfloat16_as_ushort(h0) | ((uint32_t)__bfloat16_as_ushort(h1) << 16);
            uint32_t ph1 = (uint32_t)__bfloat16_as_ushort(h2) | ((uint32_t)__bfloat16_as_ushort(h3) << 16);
            uint32_t pl0 = (uint32_t)__bfloat16_as_ushort(l0) | ((uint32_t)__bfloat16_as_ushort(l1) << 16);
            uint32_t pl1 = (uint32_t)__bfloat16_as_ushort(l2) | ((uint32_t)__bfloat16_as_ushort(l3) << 16);
            int wo = r * APADW + (c >> 1);
            Ahi[wo]     = ph0;  Ahi[wo + 1] = ph1;
            Alo[wo]     = pl0;  Alo[wo + 1] = pl1;
        }
    }
    __syncthreads();

    // Warp tiling: 16 warps, warp w covers rows (w&3)*32, cols (w>>2)*32
    int w    = tid >> 5;
    int lane = tid & 31;
    int gid  = lane >> 2;    // 0..7
    int tig  = lane & 3;     // 0..3
    int m0 = (w & 3) * 32;
    int n0 = (w >> 2) * 32;

    float acc[2][4][4];
    #pragma unroll
    for (int mt = 0; mt < 2; mt++)
        #pragma unroll
        for (int nt = 0; nt < 4; nt++)
            #pragma unroll
            for (int q = 0; q < 4; q++) acc[mt][nt][q] = 0.f;

    #pragma unroll
    for (int kc = 0; kc < 128; kc += 16) {
        int kw = kc >> 1;                    // word offset of k-chunk base
        uint32_t a_hi[2][4], a_lo[2][4], bfr[4][2];
        #pragma unroll
        for (int mt = 0; mt < 2; mt++) {
            int base = (m0 + mt * 16 + gid) * APADW + kw + tig;
            a_hi[mt][0] = Ahi[base];
            a_hi[mt][1] = Ahi[base + 8 * APADW];
            a_hi[mt][2] = Ahi[base + 4];
            a_hi[mt][3] = Ahi[base + 8 * APADW + 4];
            a_lo[mt][0] = Alo[base];
            a_lo[mt][1] = Alo[base + 8 * APADW];
            a_lo[mt][2] = Alo[base + 4];
            a_lo[mt][3] = Alo[base + 8 * APADW + 4];
        }
        // B hi: terms hi*hi and lo*hi
        #pragma unroll
        for (int nt = 0; nt < 4; nt++) {
            int base = (n0 + nt * 8 + gid) * APADW + kw + tig;
            bfr[nt][0] = Bh[base];
            bfr[nt][1] = Bh[base + 4];
        }
        #pragma unroll
        for (int mt = 0; mt < 2; mt++)
            #pragma unroll
            for (int nt = 0; nt < 4; nt++) {
                mma16816(acc[mt][nt], a_hi[mt], bfr[nt]);
                mma16816(acc[mt][nt], a_lo[mt], bfr[nt]);
            }
        // B lo: term hi*lo
        #pragma unroll
        for (int nt = 0; nt < 4; nt++) {
            int base = (n0 + nt * 8 + gid) * APADW + kw + tig;
            bfr[nt][0] = Bl[base];
            bfr[nt][1] = Bl[base + 4];
        }
        #pragma unroll
        for (int mt = 0; mt < 2; mt++)
            #pragma unroll
            for (int nt = 0; nt < 4; nt++)
                mma16816(acc[mt][nt], a_hi[mt], bfr[nt]);
    }

    // Epilogue: write fp16. c0,c1 -> (row=gid, cols tig*2+{0,1}); c2,c3 -> row=gid+8
    #pragma unroll
    for (int mt = 0; mt < 2; mt++) {
        int gr0 = row0 + m0 + mt * 16 + gid;
        #pragma unroll
        for (int nt = 0; nt < 4; nt++) {
            int col = n0 + nt * 8 + tig * 2;
            if (gr0 < n)
                *reinterpret_cast<__half2*>(Out16 + (size_t)gr0 * 128 + col) =
                    __floats2half2_rn(acc[mt][nt][0], acc[mt][nt][1]);
            if (gr0 + 8 < n)
                *reinterpret_cast<__half2*>(Out16 + (size_t)(gr0 + 8) * 128 + col) =
                    __floats2half2_rn(acc[mt][nt][2], acc[mt][nt][3]);
        }
    }
}

// ---------------- CSR aggregation (fp16 gather, unroll-4 for MLP) -----------
__device__ __forceinline__ void acc_edge(float4& acc, uint2 v, float wv) {
    float2 fa = __half22float2(*reinterpret_cast<__half2*>(&v.x));
    float2 fb = __half22float2(*reinterpret_cast<__half2*>(&v.y));
    acc.x += fa.x * wv;
    acc.y += fa.y * wv;
    acc.z += fb.x * wv;
    acc.w += fb.y * wv;
}

__device__ __forceinline__ float4 agg_row(const __half* __restrict__ h16,
                                          const float* __restrict__ bias,
                                          int i, int lane) {
    const uint2* h2 = reinterpret_cast<const uint2*>(h16);   // 32 uint2 per row
    int start = d_rowptr[i];
    int end   = d_rowptr[i + 1];
    float4 acc = make_float4(0.f, 0.f, 0.f, 0.f);

    for (int base = start; base < end; base += 32) {
        int cnt = min(32, end - base);
        int idx = 0; float nm = 0.f;
        if (lane < cnt) {
            int2 ed = d_edge[base + lane];   // one LDG.64: {src, norm}
            idx = ed.x;
            nm  = __int_as_float(ed.y);
        }
        int j = 0;
        // Unroll by 4: issue 4 independent gathers before consuming (MLP=4)
        for (; j + 4 <= cnt; j += 4) {
            int   s0 = __shfl_sync(0xffffffffu, idx, j);
            int   s1 = __shfl_sync(0xffffffffu, idx, j + 1);
            int   s2 = __shfl_sync(0xffffffffu, idx, j + 2);
            int   s3 = __shfl_sync(0xffffffffu, idx, j + 3);
            float w0 = __shfl_sync(0xffffffffu, nm, j);
            float w1 = __shfl_sync(0xffffffffu, nm, j + 1);
            float w2 = __shfl_sync(0xffffffffu, nm, j + 2);
            float w3 = __shfl_sync(0xffffffffu, nm, j + 3);
            uint2 v0 = h2[(size_t)s0 * 32 + lane];
            uint2 v1 = h2[(size_t)s1 * 32 + lane];
            uint2 v2 = h2[(size_t)s2 * 32 + lane];
            uint2 v3 = h2[(size_t)s3 * 32 + lane];
            acc_edge(acc, v0, w0);
            acc_edge(acc, v1, w1);
            acc_edge(acc, v2, w2);
            acc_edge(acc, v3, w3);
        }
        for (; j < cnt; j++) {
            int   s = __shfl_sync(0xffffffffu, idx, j);
            float wv = __shfl_sync(0xffffffffu, nm, j);
            uint2 v = h2[(size_t)s * 32 + lane];
            acc_edge(acc, v, wv);
        }
    }
    float di = d_dinv[i];
    float d2 = di * di;
    uint2 sv = h2[(size_t)i * 32 + lane];
    float2 sa = __half22float2(*reinterpret_cast<__half2*>(&sv.x));
    float2 sb = __half22float2(*reinterpret_cast<__half2*>(&sv.y));
    const float4 bv = reinterpret_cast<const float4*>(bias)[lane];
    acc.x = fmaxf(acc.x + sa.x * d2 + bv.x, 0.f);
    acc.y = fmaxf(acc.y + sa.y * d2 + bv.y, 0.f);
    acc.z = fmaxf(acc.z + sb.x * d2 + bv.z, 0.f);
    acc.w = fmaxf(acc.w + sb.y * d2 + bv.w, 0.f);
    return acc;
}

__global__ __launch_bounds__(256)
void agg_kernel(const __half* __restrict__ h16, const float* __restrict__ bias,
                float* __restrict__ out, int n) {
    int lane   = threadIdx.x & 31;
    int warp   = (blockIdx.x * blockDim.x + threadIdx.x) >> 5;
    int nwarps = (gridDim.x * blockDim.x) >> 5;
    for (int i = warp; i < n; i += nwarps) {
        float4 acc = agg_row(h16, bias, i, lane);
        reinterpret_cast<float4*>(out)[(size_t)i * 32 + lane] = acc;
    }
}

// Layer-2 agg with fused readout: out[i] = relu(agg_row) . Wlin + blin
__global__ __launch_bounds__(256)
void agg_final_kernel(const __half* __restrict__ h16, const float* __restrict__ bias,
                      const float* __restrict__ wlin, const float* __restrict__ blin,
                      float* __restrict__ out, int n) {
    int lane   = threadIdx.x & 31;
    int warp   = (blockIdx.x * blockDim.x + threadIdx.x) >> 5;
    int nwarps = (gridDim.x * blockDim.x) >> 5;
    for (int i = warp; i < n; i += nwarps) {
        float4 acc = agg_row(h16, bias, i, lane);
        float4 wv = reinterpret_cast<const float4*>(wlin)[lane];
        float s = acc.x * wv.x + acc.y * wv.y + acc.z * wv.z + acc.w * wv.w;
        #pragma unroll
        for (int off = 16; off > 0; off >>= 1)
            s += __shfl_xor_sync(0xffffffffu, s, off);
        if (lane == 0) out[i] = s + blin[0];
    }
}

// ---------------- launch ----------------------------------------------------
extern "C" void kernel_launch(void* const* d_in, const int* in_sizes, int n_in,
                              void* d_out, int out_size) {
    const float* x    = (const float*)d_in[0];
    const int*   ei   = (const int*)d_in[1];
    const float* W1   = (const float*)d_in[2];
    const float* b1   = (const float*)d_in[3];
    const float* W2   = (const float*)d_in[4];
    const float* b2   = (const float*)d_in[5];
    const float* Wlin = (const float*)d_in[6];
    const float* blin = (const float*)d_in[7];
    float* out = (float*)d_out;

    int E = in_sizes[1] / 2;
    int n = in_sizes[0] / FDIM;
    const int* src = ei;
    const int* dst = ei + E;

    int nB = (n + 255) / 256;
    int eB = (E + 255) / 256;
    int nb = (n + 1023) / 1024;
    int gB = (n + 127) / 128;

    __half* h16;  cudaGetSymbolAddress((void**)&h16, d_h16);
    float*  gbuf; cudaGetSymbolAddress((void**)&gbuf, d_g);
    int*    cntp; cudaGetSymbolAddress((void**)&cntp, d_cnt);
    __nv_bfloat16 *w1hi, *w1lo, *w2hi, *w2lo;
    cudaGetSymbolAddress((void**)&w1hi, d_w1hi);
    cudaGetSymbolAddress((void**)&w1lo, d_w1lo);
    cudaGetSymbolAddress((void**)&w2hi, d_w2hi);
    cudaGetSymbolAddress((void**)&w2lo, d_w2lo);

    const int GEMM_SMEM = 4 * TILE_WORDS * 4;   // 139264 bytes
    cudaFuncSetAttribute(gemm_mma_kernel,
                         cudaFuncAttributeMaxDynamicSharedMemorySize, GEMM_SMEM);

    // graph structure (shared by both layers) — flat single-stream chain
    cudaMemsetAsync(cntp, 0, (size_t)n * sizeof(int));
    count_kernel<<<eB, 256>>>(dst, E);
    scan1_kernel<<<nb, 1024>>>(n);
    scan2_kernel<<<1, 1024>>>(nb);
    scan3_kernel<<<nB, 256>>>(n, E);
    scatter_kernel<<<eB, 256>>>(src, dst, E);
    prep_w_kernel<<<128, 256>>>(W1, W2);

    // layer 1
    gemm_mma_kernel<<<gB, 512, GEMM_SMEM>>>(x, w1hi, w1lo, h16, n);
    agg_kernel<<<2048, 256>>>(h16, b1, gbuf, n);
    // layer 2
    gemm_mma_kernel<<<gB, 512, GEMM_SMEM>>>(gbuf, w2hi, w2lo, h16, n);
    agg_final_kernel<<<2048, 256>>>(h16, b2, Wlin, blin, out, n);
    (void)n_in; (void)out_size;
}

// round 15
// speedup vs baseline: 1.5486x; 1.0259x over previous
#include <cuda_runtime.h>
#include <cuda_bf16.h>
#include <cuda_fp16.h>
#include <cstdint>

// Problem constants (shapes fixed by the reference generator)
#define NNODES 100000
#define NEDGES 1600000
#define FDIM   128

// ---------------- scratch (static device allocations; no cudaMalloc) --------
__device__ __half d_h16[NNODES * FDIM];  // GEMM output, fp16 (gather source)
__device__ __half d_g16[NNODES * FDIM];  // layer-1 aggregated+relu output (fp16)
__device__ float  d_dinv[NNODES];
__device__ int    d_cnt[NNODES];
__device__ int    d_rowptr[NNODES + 1];
__device__ int    d_cursor[NNODES];
__device__ int    d_bsum[1024];
__device__ int2   d_edge[NEDGES];        // packed {src, norm-as-int} per CSR slot
// W pre-converted to bf16 hi/lo, stored as B[j][k] = W[k][j] (row-major, K contiguous)
__device__ __align__(16) __nv_bfloat16 d_w1hi[16384];
__device__ __align__(16) __nv_bfloat16 d_w1lo[16384];
__device__ __align__(16) __nv_bfloat16 d_w2hi[16384];
__device__ __align__(16) __nv_bfloat16 d_w2lo[16384];

// ---------------- degree / count ---------------------------------------------
__global__ void count_kernel(const int* __restrict__ dst, int E) {
    int e = blockIdx.x * blockDim.x + threadIdx.x;
    if (e < E) atomicAdd(&d_cnt[dst[e]], 1);
}

// ---------------- CSR build: 3-kernel exclusive scan + scatter --------------
__global__ void scan1_kernel(int n) {
    __shared__ int sh[1024];
    int t = threadIdx.x;
    int i = blockIdx.x * 1024 + t;
    int v = (i < n) ? d_cnt[i] : 0;
    sh[t] = v;
    __syncthreads();
    #pragma unroll
    for (int off = 1; off < 1024; off <<= 1) {
        int x = (t >= off) ? sh[t - off] : 0;
        __syncthreads();
        sh[t] += x;
        __syncthreads();
    }
    if (i < n) d_rowptr[i] = sh[t] - v;
    if (t == 1023) d_bsum[blockIdx.x] = sh[t];
}
__global__ void scan2_kernel(int nb) {
    __shared__ int sh[1024];
    int t = threadIdx.x;
    int v = (t < nb) ? d_bsum[t] : 0;
    sh[t] = v;
    __syncthreads();
    #pragma unroll
    for (int off = 1; off < 1024; off <<= 1) {
        int x = (t >= off) ? sh[t - off] : 0;
        __syncthreads();
        sh[t] += x;
        __syncthreads();
    }
    if (t < nb) d_bsum[t] = sh[t] - v;
}
// scan3 + dinv fused
__global__ void scan3_kernel(int n, int E) {
    int i = blockIdx.x * blockDim.x + threadIdx.x;
    if (i < n) {
        int r = d_rowptr[i] + d_bsum[i >> 10];
        d_rowptr[i] = r;
        d_cursor[i] = r;
        d_dinv[i] = rsqrtf((float)d_cnt[i] + 1.0f);
    }
    if (i == 0) d_rowptr[n] = E;
}
__global__ void scatter_kernel(const int* __restrict__ src,
                               const int* __restrict__ dst, int E) {
    int e = blockIdx.x * blockDim.x + threadIdx.x;
    if (e < E) {
        int s = src[e], d = dst[e];
        int p = atomicAdd(&d_cursor[d], 1);
        float nm = d_dinv[s] * d_dinv[d];
        d_edge[p] = make_int2(s, __float_as_int(nm));
    }
}

// ---------------- W pre-convert: fp32 [K,N] -> bf16 hi/lo B[j][k] -----------
__global__ void prep_w_kernel(const float* __restrict__ W1,
                              const float* __restrict__ W2) {
    int idx = blockIdx.x * blockDim.x + threadIdx.x;   // 0..32767
    if (idx >= 2 * 16384) return;
    int which = idx >> 14;
    int e = idx & 16383;
    int j = e >> 7;      // output feature (B row)
    int k = e & 127;     // input dim (B col, contiguous)
    const float* W = which ? W2 : W1;
    float w = W[k * 128 + j];
    __nv_bfloat16 hi = __float2bfloat16(w);
    __nv_bfloat16 lo = __float2bfloat16(w - __bfloat162float(hi));
    if (which) { d_w2hi[e] = hi; d_w2lo[e] = lo; }
    else       { d_w1hi[e] = hi; d_w1lo[e] = lo; }
}

// ---------------- tensor-core GEMM via mma.sync (HMMA bf16) ------------------
// Out16[n,128] = fp16( X[n,128] @ W ), fp32 accuracy via bf16 3-term split.
// Templated on input type: fp32 (layer 1) or fp16 (layer 2; exact bf16 split).
// CTA tile 128x128, 512 threads = 16 warps, warp tile 32x32 (2 m-tiles x 4 n-tiles).
#define APADW 68           // padded row stride in 32-bit words (136 bf16)
#define TILE_WORDS (128 * APADW)

__device__ __forceinline__ void mma16816(float* c, const uint32_t* a, const uint32_t* b) {
    asm volatile(
        "mma.sync.aligned.m16n8k16.row.col.f32.bf16.bf16.f32 "
        "{%0,%1,%2,%3}, {%4,%5,%6,%7}, {%8,%9}, {%0,%1,%2,%3};"
        : "+f"(c[0]), "+f"(c[1]), "+f"(c[2]), "+f"(c[3])
        : "r"(a[0]), "r"(a[1]), "r"(a[2]), "r"(a[3]), "r"(b[0]), "r"(b[1]));
}

// Load 4 consecutive input values at (row, col) as float4 (zero-padded if row>=n)
__device__ __forceinline__ float4 load_x4(const float* X, int row, int col, int n) {
    if (row >= n) return make_float4(0.f, 0.f, 0.f, 0.f);
    return *reinterpret_cast<const float4*>(X + (size_t)row * 128 + col);
}
__device__ __forceinline__ float4 load_x4(const __half* X, int row, int col, int n) {
    if (row >= n) return make_float4(0.f, 0.f, 0.f, 0.f);
    uint2 v = *reinterpret_cast<const uint2*>(X + (size_t)row * 128 + col);
    float2 fa = __half22float2(*reinterpret_cast<__half2*>(&v.x));
    float2 fb = __half22float2(*reinterpret_cast<__half2*>(&v.y));
    return make_float4(fa.x, fa.y, fb.x, fb.y);
}

template <typename TIN>
__global__ void __launch_bounds__(512, 1)
gemm_mma_kernel(const TIN* __restrict__ X,
                const __nv_bfloat16* __restrict__ Bhi_g,
                const __nv_bfloat16* __restrict__ Blo_g,
                __half* __restrict__ Out16, int n) {
    extern __shared__ uint32_t sm[];
    uint32_t* Ahi = sm;
    uint32_t* Alo = sm + TILE_WORDS;
    uint32_t* Bh  = sm + 2 * TILE_WORDS;
    uint32_t* Bl  = sm + 3 * TILE_WORDS;

    int tid  = threadIdx.x;
    int row0 = blockIdx.x * 128;

    // Copy W hi/lo tiles (128x128 bf16 = 8192 words) into padded SMEM
    {
        const uint32_t* gh = reinterpret_cast<const uint32_t*>(Bhi_g);
        const uint32_t* gl = reinterpret_cast<const uint32_t*>(Blo_g);
        #pragma unroll
        for (int i = tid; i < 8192; i += 512) {
            int r = i >> 6, c = i & 63;
            Bh[r * APADW + c] = gh[i];
            Bl[r * APADW + c] = gl[i];
        }
    }
    // Convert this tile's X rows to bf16 hi/lo into padded SMEM
    {
        int r = tid >> 2;            // 0..127
        int q = tid & 3;             // 32-col quarter
        int gr = row0 + r;
        #pragma unroll
        for (int c = q * 32; c < q * 32 + 32; c += 4) {
            float4 x4 = load_x4(X, gr, c, n);
            __nv_bfloat16 h0 = __float2bfloat16(x4.x);
            __nv_bfloat16 h1 = __float2bfloat16(x4.y);
            __nv_bfloat16 h2 = __float2bfloat16(x4.z);
            __nv_bfloat16 h3 = __float2bfloat16(x4.w);
            __nv_bfloat16 l0 = __float2bfloat16(x4.x - __bfloat162float(h0));
            __nv_bfloat16 l1 = __float2bfloat16(x4.y - __bfloat162float(h1));
            __nv_bfloat16 l2 = __float2bfloat16(x4.z - __bfloat162float(h2));
            __nv_bfloat16 l3 = __float2bfloat16(x4.w - __bfloat162float(h3));
            uint32_t ph0 = (uint32_t)__bfloat16_as_ushort(h0) | ((uint32_t)__bfloat16_as_ushort(h1) << 16);
            uint32_t ph1 = (uint32_t)__bfloat16_as_ushort(h2) | ((uint32_t)__bfloat16_as_ushort(h3) << 16);
            uint32_t pl0 = (uint32_t)__bfloat16_as_ushort(l0) | ((uint32_t)__bfloat16_as_ushort(l1) << 16);
            uint32_t pl1 = (uint32_t)__bfloat16_as_ushort(l2) | ((uint32_t)__bfloat16_as_ushort(l3) << 16);
            int wo = r * APADW + (c >> 1);
            Ahi[wo]     = ph0;  Ahi[wo + 1] = ph1;
            Alo[wo]     = pl0;  Alo[wo + 1] = pl1;
        }
    }
    __syncthreads();

    // Warp tiling: 16 warps, warp w covers rows (w&3)*32, cols (w>>2)*32
    int w    = tid >> 5;
    int lane = tid & 31;
    int gid  = lane >> 2;    // 0..7
    int tig  = lane & 3;     // 0..3
    int m0 = (w & 3) * 32;
    int n0 = (w >> 2) * 32;

    float acc[2][4][4];
    #pragma unroll
    for (int mt = 0; mt < 2; mt++)
        #pragma unroll
        for (int nt = 0; nt < 4; nt++)
            #pragma unroll
            for (int q = 0; q < 4; q++) acc[mt][nt][q] = 0.f;

    #pragma unroll
    for (int kc = 0; kc < 128; kc += 16) {
        int kw = kc >> 1;                    // word offset of k-chunk base
        uint32_t a_hi[2][4], a_lo[2][4], bfr[4][2];
        #pragma unroll
        for (int mt = 0; mt < 2; mt++) {
            int base = (m0 + mt * 16 + gid) * APADW + kw + tig;
            a_hi[mt][0] = Ahi[base];
            a_hi[mt][1] = Ahi[base + 8 * APADW];
            a_hi[mt][2] = Ahi[base + 4];
            a_hi[mt][3] = Ahi[base + 8 * APADW + 4];
            a_lo[mt][0] = Alo[base];
            a_lo[mt][1] = Alo[base + 8 * APADW];
            a_lo[mt][2] = Alo[base + 4];
            a_lo[mt][3] = Alo[base + 8 * APADW + 4];
        }
        // B hi: terms hi*hi and lo*hi
        #pragma unroll
        for (int nt = 0; nt < 4; nt++) {
            int base = (n0 + nt * 8 + gid) * APADW + kw + tig;
            bfr[nt][0] = Bh[base];
            bfr[nt][1] = Bh[base + 4];
        }
        #pragma unroll
        for (int mt = 0; mt < 2; mt++)
            #pragma unroll
            for (int nt = 0; nt < 4; nt++) {
                mma16816(acc[mt][nt], a_hi[mt], bfr[nt]);
                mma16816(acc[mt][nt], a_lo[mt], bfr[nt]);
            }
        // B lo: term hi*lo
        #pragma unroll
        for (int nt = 0; nt < 4; nt++) {
            int base = (n0 + nt * 8 + gid) * APADW + kw + tig;
            bfr[nt][0] = Bl[base];
            bfr[nt][1] = Bl[base + 4];
        }
        #pragma unroll
        for (int mt = 0; mt < 2; mt++)
            #pragma unroll
            for (int nt = 0; nt < 4; nt++)
                mma16816(acc[mt][nt], a_hi[mt], bfr[nt]);
    }

    // Epilogue: write fp16. c0,c1 -> (row=gid, cols tig*2+{0,1}); c2,c3 -> row=gid+8
    #pragma unroll
    for (int mt = 0; mt < 2; mt++) {
        int gr0 = row0 + m0 + mt * 16 + gid;
        #pragma unroll
        for (int nt = 0; nt < 4; nt++) {
            int col = n0 + nt * 8 + tig * 2;
            if (gr0 < n)
                *reinterpret_cast<__half2*>(Out16 + (size_t)gr0 * 128 + col) =
                    __floats2half2_rn(acc[mt][nt][0], acc[mt][nt][1]);
            if (gr0 + 8 < n)
                *reinterpret_cast<__half2*>(Out16 + (size_t)(gr0 + 8) * 128 + col) =
                    __floats2half2_rn(acc[mt][nt][2], acc[mt][nt][3]);
        }
    }
}

// ---------------- CSR aggregation (fp16 gather, unroll-4 for MLP) -----------
__device__ __forceinline__ void acc_edge(float4& acc, uint2 v, float wv) {
    float2 fa = __half22float2(*reinterpret_cast<__half2*>(&v.x));
    float2 fb = __half22float2(*reinterpret_cast<__half2*>(&v.y));
    acc.x += fa.x * wv;
    acc.y += fa.y * wv;
    acc.z += fb.x * wv;
    acc.w += fb.y * wv;
}

__device__ __forceinline__ float4 agg_row(const __half* __restrict__ h16,
                                          const float* __restrict__ bias,
                                          int i, int lane) {
    const uint2* h2 = reinterpret_cast<const uint2*>(h16);   // 32 uint2 per row
    int start = d_rowptr[i];
    int end   = d_rowptr[i + 1];
    float4 acc = make_float4(0.f, 0.f, 0.f, 0.f);

    for (int base = start; base < end; base += 32) {
        int cnt = min(32, end - base);
        int idx = 0; float nm = 0.f;
        if (lane < cnt) {
            int2 ed = d_edge[base + lane];   // one LDG.64: {src, norm}
            idx = ed.x;
            nm  = __int_as_float(ed.y);
        }
        int j = 0;
        // Unroll by 4: issue 4 independent gathers before consuming (MLP=4)
        for (; j + 4 <= cnt; j += 4) {
            int   s0 = __shfl_sync(0xffffffffu, idx, j);
            int   s1 = __shfl_sync(0xffffffffu, idx, j + 1);
            int   s2 = __shfl_sync(0xffffffffu, idx, j + 2);
            int   s3 = __shfl_sync(0xffffffffu, idx, j + 3);
            float w0 = __shfl_sync(0xffffffffu, nm, j);
            float w1 = __shfl_sync(0xffffffffu, nm, j + 1);
            float w2 = __shfl_sync(0xffffffffu, nm, j + 2);
            float w3 = __shfl_sync(0xffffffffu, nm, j + 3);
            uint2 v0 = h2[(size_t)s0 * 32 + lane];
            uint2 v1 = h2[(size_t)s1 * 32 + lane];
            uint2 v2 = h2[(size_t)s2 * 32 + lane];
            uint2 v3 = h2[(size_t)s3 * 32 + lane];
            acc_edge(acc, v0, w0);
            acc_edge(acc, v1, w1);
            acc_edge(acc, v2, w2);
            acc_edge(acc, v3, w3);
        }
        for (; j < cnt; j++) {
            int   s = __shfl_sync(0xffffffffu, idx, j);
            float wv = __shfl_sync(0xffffffffu, nm, j);
            uint2 v = h2[(size_t)s * 32 + lane];
            acc_edge(acc, v, wv);
        }
    }
    float di = d_dinv[i];
    float d2 = di * di;
    uint2 sv = h2[(size_t)i * 32 + lane];
    float2 sa = __half22float2(*reinterpret_cast<__half2*>(&sv.x));
    float2 sb = __half22float2(*reinterpret_cast<__half2*>(&sv.y));
    const float4 bv = reinterpret_cast<const float4*>(bias)[lane];
    acc.x = fmaxf(acc.x + sa.x * d2 + bv.x, 0.f);
    acc.y = fmaxf(acc.y + sa.y * d2 + bv.y, 0.f);
    acc.z = fmaxf(acc.z + sb.x * d2 + bv.z, 0.f);
    acc.w = fmaxf(acc.w + sb.y * d2 + bv.w, 0.f);
    return acc;
}

// Layer-1 agg: writes fp16 g buffer (halves boundary traffic with GEMM-2)
__global__ __launch_bounds__(256)
void agg_kernel(const __half* __restrict__ h16, const float* __restrict__ bias,
                __half* __restrict__ out16, int n) {
    int lane   = threadIdx.x & 31;
    int warp   = (blockIdx.x * blockDim.x + threadIdx.x) >> 5;
    int nwarps = (gridDim.x * blockDim.x) >> 5;
    for (int i = warp; i < n; i += nwarps) {
        float4 acc = agg_row(h16, bias, i, lane);
        __half2 p0 = __floats2half2_rn(acc.x, acc.y);
        __half2 p1 = __floats2half2_rn(acc.z, acc.w);
        uint2 pk;
        pk.x = *reinterpret_cast<uint32_t*>(&p0);
        pk.y = *reinterpret_cast<uint32_t*>(&p1);
        reinterpret_cast<uint2*>(out16)[(size_t)i * 32 + lane] = pk;
    }
}

// Layer-2 agg with fused readout: out[i] = relu(agg_row) . Wlin + blin
__global__ __launch_bounds__(256)
void agg_final_kernel(const __half* __restrict__ h16, const float* __restrict__ bias,
                      const float* __restrict__ wlin, const float* __restrict__ blin,
                      float* __restrict__ out, int n) {
    int lane   = threadIdx.x & 31;
    int warp   = (blockIdx.x * blockDim.x + threadIdx.x) >> 5;
    int nwarps = (gridDim.x * blockDim.x) >> 5;
    for (int i = warp; i < n; i += nwarps) {
        float4 acc = agg_row(h16, bias, i, lane);
        float4 wv = reinterpret_cast<const float4*>(wlin)[lane];
        float s = acc.x * wv.x + acc.y * wv.y + acc.z * wv.z + acc.w * wv.w;
        #pragma unroll
        for (int off = 16; off > 0; off >>= 1)
            s += __shfl_xor_sync(0xffffffffu, s, off);
        if (lane == 0) out[i] = s + blin[0];
    }
}

// ---------------- launch ----------------------------------------------------
extern "C" void kernel_launch(void* const* d_in, const int* in_sizes, int n_in,
                              void* d_out, int out_size) {
    const float* x    = (const float*)d_in[0];
    const int*   ei   = (const int*)d_in[1];
    const float* W1   = (const float*)d_in[2];
    const float* b1   = (const float*)d_in[3];
    const float* W2   = (const float*)d_in[4];
    const float* b2   = (const float*)d_in[5];
    const float* Wlin = (const float*)d_in[6];
    const float* blin = (const float*)d_in[7];
    float* out = (float*)d_out;

    int E = in_sizes[1] / 2;
    int n = in_sizes[0] / FDIM;
    const int* src = ei;
    const int* dst = ei + E;

    int nB = (n + 255) / 256;
    int eB = (E + 255) / 256;
    int nb = (n + 1023) / 1024;
    int gB = (n + 127) / 128;

    __half* h16;  cudaGetSymbolAddress((void**)&h16, d_h16);
    __half* g16;  cudaGetSymbolAddress((void**)&g16, d_g16);
    int*    cntp; cudaGetSymbolAddress((void**)&cntp, d_cnt);
    __nv_bfloat16 *w1hi, *w1lo, *w2hi, *w2lo;
    cudaGetSymbolAddress((void**)&w1hi, d_w1hi);
    cudaGetSymbolAddress((void**)&w1lo, d_w1lo);
    cudaGetSymbolAddress((void**)&w2hi, d_w2hi);
    cudaGetSymbolAddress((void**)&w2lo, d_w2lo);

    const int GEMM_SMEM = 4 * TILE_WORDS * 4;   // 139264 bytes
    cudaFuncSetAttribute(gemm_mma_kernel<float>,
                         cudaFuncAttributeMaxDynamicSharedMemorySize, GEMM_SMEM);
    cudaFuncSetAttribute(gemm_mma_kernel<__half>,
                         cudaFuncAttributeMaxDynamicSharedMemorySize, GEMM_SMEM);

    // graph structure (shared by both layers) — flat single-stream chain
    cudaMemsetAsync(cntp, 0, (size_t)n * sizeof(int));
    count_kernel<<<eB, 256>>>(dst, E);
    scan1_kernel<<<nb, 1024>>>(n);
    scan2_kernel<<<1, 1024>>>(nb);
    scan3_kernel<<<nB, 256>>>(n, E);
    scatter_kernel<<<eB, 256>>>(src, dst, E);
    prep_w_kernel<<<128, 256>>>(W1, W2);

    // layer 1
    gemm_mma_kernel<float><<<gB, 512, GEMM_SMEM>>>(x, w1hi, w1lo, h16, n);
    agg_kernel<<<2048, 256>>>(h16, b1, g16, n);
    // layer 2
    gemm_mma_kernel<__half><<<gB, 512, GEMM_SMEM>>>(g16, w2hi, w2lo, h16, n);
    agg_final_kernel<<<2048, 256>>>(h16, b2, Wlin, blin, out, n);
    (void)n_in; (void)out_size;
}